// round 13
// baseline (speedup 1.0000x reference)
#include <cuda_runtime.h>
#include <cuda_bf16.h>
#include <cuda_fp16.h>
#include <cstdint>

#define N_NODES  50000
#define N_EDGES  800000
#define IN_FEAT  256
#define OUT_FEAT 128
#define P_EDGE   0.2f
#define P_NODE   0.1f
#define BN_EPS   1e-5f

#define SCAN_CHUNK  256
#define SCAN_BLOCKS ((N_NODES + SCAN_CHUNK - 1) / SCAN_CHUNK)   // 196

// ----------------------------- scratch (no allocs allowed) ------------------
// NOTE: module-load zero-init covers the first call; every invocation
// re-zeroes what the next one needs (g_sum/g_sumsq in k_scatter, counters +
// scan flags at the tail of k_aggfin). Graph-replay safe by construction.
__device__ __half             g_h[(size_t)N_NODES * OUT_FEAT];   // fp16 h
__device__ float              g_agg[(size_t)N_NODES * OUT_FEAT];
__device__ int                g_cnt_src[N_NODES];
__device__ int                g_cnt_dst[N_NODES];
__device__ float              g_rs_src[N_NODES];
__device__ float              g_rs_dst[N_NODES];
__device__ int                g_off[N_NODES + 1];
__device__ int                g_rank[N_EDGES];    // per-edge rank within dst
__device__ unsigned long long g_scan[SCAN_BLOCKS];
__device__ long long          g_rec[N_EDGES];     // packed {lo: src, hi: coef}
__device__ float              g_sum[OUT_FEAT];
__device__ float              g_sumsq[OUT_FEAT];
__device__ int                g_bar_cnt;          // grid barrier (self-restoring)
__device__ volatile int       g_bar_sense;
__device__ unsigned short     g_wtb_hi[OUT_FEAT * IN_FEAT];
__device__ unsigned short     g_wtb_lo[OUT_FEAT * IN_FEAT];

__device__ __forceinline__ int get_idx(const void* p, int e, int is64) {
    return is64 ? (int)((const long long*)p)[e] : ((const int*)p)[e];
}

// per-block dtype sniff: int64 indices < 2^31 have zero high words; 16
// consecutive zero odd-words from random int32 data has probability ~1e-75.
__device__ __forceinline__ int sniff_is64(const void* src) {
    const unsigned* p = (const unsigned*)src;
    int is64 = 1;
#pragma unroll
    for (int k = 0; k < 16; k++) is64 &= (p[2 * k + 1] == 0u);
    return is64;
}

// sense-reversing grid barrier; requires all nblk blocks co-resident.
__device__ __forceinline__ void grid_barrier(int nblk) {
    __syncthreads();
    if (threadIdx.x == 0) {
        int s = g_bar_sense;
        __threadfence();
        if (atomicAdd(&g_bar_cnt, 1) == nblk - 1) {
            g_bar_cnt = 0;
            __threadfence();
            g_bar_sense = s ^ 1;
        } else {
            while (g_bar_sense == s) { }
        }
    }
    __syncthreads();
}

// --------------- degrees + per-edge dst-rank (reuse atomic return) ----------
__global__ __launch_bounds__(256)
void k_deg(const void* __restrict__ src, const void* __restrict__ dst,
           const float* __restrict__ er) {
    __shared__ int s64;
    if (threadIdx.x == 0) s64 = sniff_is64(src);
    __syncthreads();
    int e = blockIdx.x * blockDim.x + threadIdx.x;
    if (e >= N_EDGES) return;
    float ev = __ldg(er + e);
    int is64 = s64;
    int s = get_idx(src, e, is64);
    int d = get_idx(dst, e, is64);
    if (ev >= P_EDGE) {
        atomicAdd(&g_cnt_src[s], 1);
        int r = atomicAdd(&g_cnt_dst[d], 1);
        g_rank[e] = r;
    }
}

// --------------- single-launch decoupled-lookback scan ----------------------
__global__ __launch_bounds__(SCAN_CHUNK)
void k_scan_lb() {
    const int b    = blockIdx.x;
    const int t    = threadIdx.x;
    const int lane = t & 31;
    const int w    = t >> 5;
    const int i    = b * SCAN_CHUNK + t;

    int v = (i < N_NODES) ? g_cnt_dst[i] : 0;
    int incl = v;
#pragma unroll
    for (int o = 1; o < 32; o <<= 1) {
        int n = __shfl_up_sync(~0u, incl, o);
        if (lane >= o) incl += n;
    }
    __shared__ int ws[SCAN_CHUNK / 32];
    if (lane == 31) ws[w] = incl;
    __syncthreads();
    if (w == 0 && lane < SCAN_CHUNK / 32) {
        int x = ws[lane];
#pragma unroll
        for (int o = 1; o < SCAN_CHUNK / 32; o <<= 1) {
            int n = __shfl_up_sync(0xffu, x, o);
            if (lane >= o) x += n;
        }
        ws[lane] = x;
    }
    __syncthreads();
    int wbase = (w > 0) ? ws[w - 1] : 0;
    int total = ws[SCAN_CHUNK / 32 - 1];
    int lexcl = wbase + incl - v;

    __shared__ int s_excl;
    if (t == 0) {
        if (b == 0) {
            atomicExch(&g_scan[0], ((unsigned long long)total << 2) | 2ull);
            s_excl = 0;
        } else {
            atomicExch(&g_scan[b], ((unsigned long long)total << 2) | 1ull);
        }
    }
    __syncthreads();

    if (b > 0 && w == 0) {
        long long excl = 0;
        int p = b - 1;
        for (;;) {
            int idx = p - lane;
            unsigned long long pk = 0;
            int flag = 2;
            if (idx >= 0) {
                do {
                    pk = *(volatile unsigned long long*)&g_scan[idx];
                    flag = (int)(pk & 3ull);
                } while (flag == 0);
            }
            unsigned pmask = __ballot_sync(~0u, (idx >= 0) && (flag == 2));
            int stop = pmask ? (__ffs(pmask) - 1) : 32;
            long long val = (long long)(pk >> 2);
            long long contrib = ((idx >= 0) && (lane <= stop)) ? val : 0;
#pragma unroll
            for (int o = 16; o > 0; o >>= 1)
                contrib += __shfl_down_sync(~0u, contrib, o);
            contrib = __shfl_sync(~0u, contrib, 0);
            excl += contrib;
            if (stop < 32) break;
            p -= 32;
        }
        if (lane == 0) {
            atomicExch(&g_scan[b],
                       (((unsigned long long)(excl + total)) << 2) | 2ull);
            s_excl = (int)excl;
        }
    }
    __syncthreads();
    int excl = s_excl;

    if (i < N_NODES) {
        int off = excl + lexcl;
        g_off[i] = off;
        g_rs_src[i] = rsqrtf(fmaxf((float)g_cnt_src[i], 1.f));
        g_rs_dst[i] = rsqrtf(fmaxf((float)v, 1.f));
        if (i == N_NODES - 1) g_off[N_NODES] = off + v;
    }
}

// --------------- scatter (atomic-free) + zero BN accumulators ---------------
__global__ __launch_bounds__(256)
void k_scatter(const void* __restrict__ src, const void* __restrict__ dst,
               const float* __restrict__ er) {
    __shared__ int s64;
    if (threadIdx.x == 0) s64 = sniff_is64(src);
    __syncthreads();
    int e = blockIdx.x * blockDim.x + threadIdx.x;
    // pre-zero BN accumulators for the upcoming k_aggfin (stream-ordered)
    if (blockIdx.x == 0 && threadIdx.x < OUT_FEAT) {
        g_sum[threadIdx.x] = 0.f;
        g_sumsq[threadIdx.x] = 0.f;
    }
    if (e >= N_EDGES) return;
    float ev = __ldg(er + e);
    int is64 = s64;
    int s = get_idx(src, e, is64);
    int d = get_idx(dst, e, is64);
    if (ev < P_EDGE) return;
    float coef = g_rs_src[s] * g_rs_dst[d];
    int pos = g_off[d] + g_rank[e];
    g_rec[pos] = (long long)(unsigned)s |
                 ((long long)(unsigned)__float_as_int(coef) << 32);
}

// ----------------------------- W^T bf16 hi/lo precompute --------------------
__global__ __launch_bounds__(256)
void k_wprep(const float* __restrict__ W) {
    int idx = blockIdx.x * blockDim.x + threadIdx.x;
    if (idx >= OUT_FEAT * IN_FEAT) return;
    int n = idx >> 8, k = idx & 255;
    float v = W[k * OUT_FEAT + n];
    __nv_bfloat16 hb = __float2bfloat16_rn(v);
    float r = v - __bfloat162float(hb);
    __nv_bfloat16 lb = __float2bfloat16_rn(r);
    g_wtb_hi[idx] = *(unsigned short*)&hb;
    g_wtb_lo[idx] = *(unsigned short*)&lb;
}

// ----------------------------- GEMM: mma.sync bf16 3-pass, fp16 output ------
#define APITCH 40
#define KCH    32
#define GSM_BYTES (4 * 128 * APITCH * 2)   // 40960

__device__ __forceinline__ void mma16816(float* d, const uint32_t* a,
                                         const uint32_t* b) {
    asm volatile(
        "mma.sync.aligned.m16n8k16.row.col.f32.bf16.bf16.f32 "
        "{%0,%1,%2,%3}, {%4,%5,%6,%7}, {%8,%9}, {%0,%1,%2,%3};"
        : "+f"(d[0]), "+f"(d[1]), "+f"(d[2]), "+f"(d[3])
        : "r"(a[0]), "r"(a[1]), "r"(a[2]), "r"(a[3]), "r"(b[0]), "r"(b[1]));
}

__global__ __launch_bounds__(256, 2)
void k_gemm_mma(const float* __restrict__ A) {
    extern __shared__ __align__(16) unsigned short sm[];
    unsigned short* Ahi = sm;
    unsigned short* Alo = Ahi + 128 * APITCH;
    unsigned short* Bhi = Alo + 128 * APITCH;
    unsigned short* Blo = Bhi + 128 * APITCH;

    const int tid  = threadIdx.x;
    const int lane = tid & 31;
    const int wid  = tid >> 5;
    const int wm   = wid >> 2;
    const int wn   = wid & 3;
    const int rowb = blockIdx.x * 128;
    const int gr4  = lane >> 2;
    const int kq   = (lane & 3) * 2;

    float acc[4][4][4];
#pragma unroll
    for (int mt = 0; mt < 4; mt++)
#pragma unroll
        for (int nt = 0; nt < 4; nt++)
#pragma unroll
            for (int r = 0; r < 4; r++) acc[mt][nt][r] = 0.f;

    for (int ch = 0; ch < IN_FEAT / KCH; ch++) {
        const int kt = ch * KCH;
#pragma unroll
        for (int it = 0; it < 4; it++) {
            int idx = it * 256 + tid;
            int row = idx >> 3;
            int q   = idx & 7;
            int gr  = rowb + row;
            float4 v = (gr < N_NODES)
                ? ((const float4*)(A + (size_t)gr * IN_FEAT + kt + q * 4))[0]
                : make_float4(0.f, 0.f, 0.f, 0.f);
            __nv_bfloat16 h0 = __float2bfloat16_rn(v.x);
            __nv_bfloat16 h1 = __float2bfloat16_rn(v.y);
            __nv_bfloat16 h2 = __float2bfloat16_rn(v.z);
            __nv_bfloat16 h3 = __float2bfloat16_rn(v.w);
            __nv_bfloat16 l0 = __float2bfloat16_rn(v.x - __bfloat162float(h0));
            __nv_bfloat16 l1 = __float2bfloat16_rn(v.y - __bfloat162float(h1));
            __nv_bfloat16 l2 = __float2bfloat16_rn(v.z - __bfloat162float(h2));
            __nv_bfloat16 l3 = __float2bfloat16_rn(v.w - __bfloat162float(h3));
            uint2 hp, lp;
            hp.x = (uint32_t)*(unsigned short*)&h0 | ((uint32_t)*(unsigned short*)&h1 << 16);
            hp.y = (uint32_t)*(unsigned short*)&h2 | ((uint32_t)*(unsigned short*)&h3 << 16);
            lp.x = (uint32_t)*(unsigned short*)&l0 | ((uint32_t)*(unsigned short*)&l1 << 16);
            lp.y = (uint32_t)*(unsigned short*)&l2 | ((uint32_t)*(unsigned short*)&l3 << 16);
            *(uint2*)(Ahi + row * APITCH + q * 4) = hp;
            *(uint2*)(Alo + row * APITCH + q * 4) = lp;
        }
#pragma unroll
        for (int it = 0; it < 4; it++) {
            int idx = it * 256 + tid;
            int row = idx >> 3;
            int q   = idx & 7;
            uint2 hp = *(const uint2*)(g_wtb_hi + (size_t)row * IN_FEAT + kt + q * 4);
            uint2 lp = *(const uint2*)(g_wtb_lo + (size_t)row * IN_FEAT + kt + q * 4);
            *(uint2*)(Bhi + row * APITCH + q * 4) = hp;
            *(uint2*)(Blo + row * APITCH + q * 4) = lp;
        }
        __syncthreads();

#pragma unroll
        for (int ks = 0; ks < KCH; ks += 16) {
            uint32_t bh[4][2], bl[4][2];
#pragma unroll
            for (int nt = 0; nt < 4; nt++) {
                int n0 = wn * 32 + nt * 8 + gr4;
                const unsigned short* ph = Bhi + n0 * APITCH + ks + kq;
                const unsigned short* pl = Blo + n0 * APITCH + ks + kq;
                bh[nt][0] = *(const uint32_t*)ph;
                bh[nt][1] = *(const uint32_t*)(ph + 8);
                bl[nt][0] = *(const uint32_t*)pl;
                bl[nt][1] = *(const uint32_t*)(pl + 8);
            }
            uint32_t ah[4][4], al[4][4];
#pragma unroll
            for (int mt = 0; mt < 4; mt++) {
                int m0 = wm * 64 + mt * 16 + gr4;
                const unsigned short* ph = Ahi + m0 * APITCH + ks + kq;
                const unsigned short* pl = Alo + m0 * APITCH + ks + kq;
                ah[mt][0] = *(const uint32_t*)ph;
                ah[mt][1] = *(const uint32_t*)(ph + 8 * APITCH);
                ah[mt][2] = *(const uint32_t*)(ph + 8);
                ah[mt][3] = *(const uint32_t*)(ph + 8 * APITCH + 8);
                al[mt][0] = *(const uint32_t*)pl;
                al[mt][1] = *(const uint32_t*)(pl + 8 * APITCH);
                al[mt][2] = *(const uint32_t*)(pl + 8);
                al[mt][3] = *(const uint32_t*)(pl + 8 * APITCH + 8);
            }
#pragma unroll
            for (int mt = 0; mt < 4; mt++)
#pragma unroll
                for (int nt = 0; nt < 4; nt++)
                    mma16816(acc[mt][nt], ah[mt], bh[nt]);
#pragma unroll
            for (int mt = 0; mt < 4; mt++)
#pragma unroll
                for (int nt = 0; nt < 4; nt++)
                    mma16816(acc[mt][nt], al[mt], bh[nt]);
#pragma unroll
            for (int mt = 0; mt < 4; mt++)
#pragma unroll
                for (int nt = 0; nt < 4; nt++)
                    mma16816(acc[mt][nt], ah[mt], bl[nt]);
        }
        __syncthreads();
    }

#pragma unroll
    for (int mt = 0; mt < 4; mt++) {
        int r0 = rowb + wm * 64 + mt * 16 + gr4;
#pragma unroll
        for (int nt = 0; nt < 4; nt++) {
            int c0 = wn * 32 + nt * 8 + (lane & 3) * 2;
            if (r0 < N_NODES)
                *(__half2*)(g_h + (size_t)r0 * OUT_FEAT + c0) =
                    __floats2half2_rn(acc[mt][nt][0], acc[mt][nt][1]);
            if (r0 + 8 < N_NODES)
                *(__half2*)(g_h + (size_t)(r0 + 8) * OUT_FEAT + c0) =
                    __floats2half2_rn(acc[mt][nt][2], acc[mt][nt][3]);
        }
    }
}

// --------- fused: aggregate + BN stats + grid barrier + BN apply + dropout --
__global__ __launch_bounds__(256)
void k_aggfin(const float* __restrict__ b, const float* __restrict__ nr,
              const float* __restrict__ gamma, const float* __restrict__ beta,
              float* __restrict__ out, int nblk) {
    const int lane  = threadIdx.x & 31;
    const int wid   = threadIdx.x >> 5;
    const int wg    = (blockIdx.x * blockDim.x + threadIdx.x) >> 5;
    const int nwarp = nblk * (256 >> 5);

    float4 bb = __ldg(((const float4*)b) + lane);
    float s0 = 0.f, s1 = 0.f, s2 = 0.f, s3 = 0.f;
    float q0 = 0.f, q1 = 0.f, q2 = 0.f, q3 = 0.f;

    for (int node = wg; node < N_NODES; node += nwarp) {
        int beg = g_off[node];
        int end = g_off[node + 1];
        float4 acc = bb;
        int j = beg;
        for (; j + 4 <= end; j += 4) {
            long long r0 = __ldg(g_rec + j + 0);
            long long r1 = __ldg(g_rec + j + 1);
            long long r2 = __ldg(g_rec + j + 2);
            long long r3 = __ldg(g_rec + j + 3);
            const uint2* p0 = (const uint2*)(g_h + (size_t)(unsigned)(int)r0 * OUT_FEAT) + lane;
            const uint2* p1 = (const uint2*)(g_h + (size_t)(unsigned)(int)r1 * OUT_FEAT) + lane;
            const uint2* p2 = (const uint2*)(g_h + (size_t)(unsigned)(int)r2 * OUT_FEAT) + lane;
            const uint2* p3 = (const uint2*)(g_h + (size_t)(unsigned)(int)r3 * OUT_FEAT) + lane;
            uint2 u0 = __ldg(p0);
            uint2 u1 = __ldg(p1);
            uint2 u2 = __ldg(p2);
            uint2 u3 = __ldg(p3);
            float c0 = __int_as_float((int)(r0 >> 32));
            float c1 = __int_as_float((int)(r1 >> 32));
            float c2 = __int_as_float((int)(r2 >> 32));
            float c3 = __int_as_float((int)(r3 >> 32));
            float2 a0 = __half22float2(*(__half2*)&u0.x), b0 = __half22float2(*(__half2*)&u0.y);
            float2 a1 = __half22float2(*(__half2*)&u1.x), b1 = __half22float2(*(__half2*)&u1.y);
            float2 a2 = __half22float2(*(__half2*)&u2.x), b2 = __half22float2(*(__half2*)&u2.y);
            float2 a3 = __half22float2(*(__half2*)&u3.x), b3 = __half22float2(*(__half2*)&u3.y);
            acc.x = fmaf(c0, a0.x, acc.x); acc.y = fmaf(c0, a0.y, acc.y);
            acc.z = fmaf(c0, b0.x, acc.z); acc.w = fmaf(c0, b0.y, acc.w);
            acc.x = fmaf(c1, a1.x, acc.x); acc.y = fmaf(c1, a1.y, acc.y);
            acc.z = fmaf(c1, b1.x, acc.z); acc.w = fmaf(c1, b1.y, acc.w);
            acc.x = fmaf(c2, a2.x, acc.x); acc.y = fmaf(c2, a2.y, acc.y);
            acc.z = fmaf(c2, b2.x, acc.z); acc.w = fmaf(c2, b2.y, acc.w);
            acc.x = fmaf(c3, a3.x, acc.x); acc.y = fmaf(c3, a3.y, acc.y);
            acc.z = fmaf(c3, b3.x, acc.z); acc.w = fmaf(c3, b3.y, acc.w);
        }
        for (; j < end; j++) {
            long long r = __ldg(g_rec + j);
            int   s  = (int)(unsigned)r;
            float cf = __int_as_float((int)(r >> 32));
            uint2 u = __ldg((const uint2*)(g_h + (size_t)s * OUT_FEAT) + lane);
            float2 a = __half22float2(*(__half2*)&u.x);
            float2 c = __half22float2(*(__half2*)&u.y);
            acc.x = fmaf(cf, a.x, acc.x);
            acc.y = fmaf(cf, a.y, acc.y);
            acc.z = fmaf(cf, c.x, acc.z);
            acc.w = fmaf(cf, c.y, acc.w);
        }
        ((float4*)(g_agg + (size_t)node * OUT_FEAT))[lane] = acc;
        s0 += acc.x; s1 += acc.y; s2 += acc.z; s3 += acc.w;
        q0 += acc.x * acc.x; q1 += acc.y * acc.y;
        q2 += acc.z * acc.z; q3 += acc.w * acc.w;
    }

    __shared__ __align__(16) float smS[8][128];
    __shared__ __align__(16) float smQ[8][128];
    ((float4*)&smS[wid][lane * 4])[0] = make_float4(s0, s1, s2, s3);
    ((float4*)&smQ[wid][lane * 4])[0] = make_float4(q0, q1, q2, q3);
    __syncthreads();
    if (threadIdx.x < 128) {
        int c = threadIdx.x;
        float ts = 0.f, tq = 0.f;
#pragma unroll
        for (int w = 0; w < 8; w++) { ts += smS[w][c]; tq += smQ[w][c]; }
        atomicAdd(&g_sum[c], ts);
        atomicAdd(&g_sumsq[c], tq);
    }

    // ---- all blocks are one resident wave: grid-wide barrier
    __threadfence();
    grid_barrier(nblk);

    // ---- BN params for this lane's 4 columns
    const float inv_n = 1.f / (float)N_NODES;
    const float inv_keep = 1.f / (1.f - P_NODE);
    float scl[4], shf[4];
#pragma unroll
    for (int t = 0; t < 4; t++) {
        int c = lane * 4 + t;
        float mean = g_sum[c] * inv_n;
        float var  = g_sumsq[c] * inv_n - mean * mean;
        float sc   = rsqrtf(var + BN_EPS) * __ldg(gamma + c);
        scl[t] = sc * inv_keep;
        shf[t] = (__ldg(beta + c) - mean * sc) * inv_keep;
    }

    // ---- apply BN + node dropout to this warp's nodes (g_agg is L2-hot)
    for (int node = wg; node < N_NODES; node += nwarp) {
        float4 a = ((const float4*)(g_agg + (size_t)node * OUT_FEAT))[lane];
        float4 r = __ldg((const float4*)(nr + (size_t)node * OUT_FEAT) + lane);
        float4 y;
        y.x = (r.x >= P_NODE) ? a.x * scl[0] + shf[0] : 0.f;
        y.y = (r.y >= P_NODE) ? a.y * scl[1] + shf[1] : 0.f;
        y.z = (r.z >= P_NODE) ? a.z * scl[2] + shf[2] : 0.f;
        y.w = (r.w >= P_NODE) ? a.w * scl[3] + shf[3] : 0.f;
        ((float4*)(out + (size_t)node * OUT_FEAT))[lane] = y;
    }

    // ---- cleanup for next replay (stream-ordered before next call's k_deg)
    int gi = blockIdx.x * blockDim.x + threadIdx.x;
    if (gi < N_NODES) { g_cnt_src[gi] = 0; g_cnt_dst[gi] = 0; }
    if (gi < SCAN_BLOCKS) g_scan[gi] = 0ull;
}

// ----------------------------- launch ---------------------------------------
extern "C" void kernel_launch(void* const* d_in, const int* in_sizes, int n_in,
                              void* d_out, int out_size) {
    const float* features = (const float*)d_in[0];
    const float* W        = (const float*)d_in[1];
    const float* b        = (const float*)d_in[2];
    const float* gamma    = (const float*)d_in[3];
    const float* beta     = (const float*)d_in[4];
    const void*  src      = d_in[5];
    const void*  dst      = d_in[6];
    const float* er       = (const float*)d_in[7];
    const float* nr       = (const float*)d_in[8];
    float* out            = (float*)d_out;

    static cudaStream_t s_side = nullptr;
    static cudaEvent_t  s_fork = nullptr, s_join = nullptr;
    static int          s_grid = 0;
    if (s_side == nullptr) {
        cudaStreamCreateWithFlags(&s_side, cudaStreamNonBlocking);
        cudaEventCreateWithFlags(&s_fork, cudaEventDisableTiming);
        cudaEventCreateWithFlags(&s_join, cudaEventDisableTiming);
        cudaFuncSetAttribute(k_gemm_mma,
                             cudaFuncAttributeMaxDynamicSharedMemorySize,
                             GSM_BYTES);
        // one resident wave for the fused kernel (grid barrier requires it)
        int nsm = 0, occ = 0;
        cudaDeviceGetAttribute(&nsm, cudaDevAttrMultiProcessorCount, 0);
        cudaOccupancyMaxActiveBlocksPerMultiprocessor(&occ, k_aggfin, 256, 0);
        if (nsm <= 0) nsm = 148;
        if (occ <= 0) occ = 1;
        s_grid = nsm * occ;
    }

    // fork: GEMM branch (features/W only) on side stream
    cudaEventRecord(s_fork, 0);
    cudaStreamWaitEvent(s_side, s_fork, 0);
    k_wprep<<<(OUT_FEAT * IN_FEAT + 255) / 256, 256, 0, s_side>>>(W);
    k_gemm_mma<<<(N_NODES + 127) / 128, 256, GSM_BYTES, s_side>>>(features);
    cudaEventRecord(s_join, s_side);

    // main branch: edge chain (no init kernel — state pre-zeroed by prior call)
    k_deg<<<(N_EDGES + 255) / 256, 256>>>(src, dst, er);
    k_scan_lb<<<SCAN_BLOCKS, SCAN_CHUNK>>>();
    k_scatter<<<(N_EDGES + 255) / 256, 256>>>(src, dst, er);

    // join: fused aggregation + BN + dropout
    cudaStreamWaitEvent(0, s_join, 0);
    k_aggfin<<<s_grid, 256>>>(b, nr, gamma, beta, out, s_grid);
}

// round 14
// speedup vs baseline: 1.0235x; 1.0235x over previous
#include <cuda_runtime.h>
#include <cuda_bf16.h>
#include <cuda_fp16.h>
#include <cstdint>

#define N_NODES  50000
#define N_EDGES  800000
#define IN_FEAT  256
#define OUT_FEAT 128
#define P_EDGE   0.2f
#define P_NODE   0.1f
#define BN_EPS   1e-5f

#define SCAN_CHUNK  256
#define SCAN_BLOCKS ((N_NODES + SCAN_CHUNK - 1) / SCAN_CHUNK)   // 196

// ----------------------------- scratch (no allocs allowed) ------------------
__device__ __half             g_h[(size_t)N_NODES * OUT_FEAT];
__device__ float              g_agg[(size_t)N_NODES * OUT_FEAT];
__device__ int                g_cnt_src[N_NODES];
__device__ int                g_cnt_dst[N_NODES];
__device__ float              g_rs_src[N_NODES];
__device__ float              g_rs_dst[N_NODES];
__device__ int                g_off[N_NODES + 1];
__device__ int                g_rank[N_EDGES];
__device__ unsigned long long g_scan[SCAN_BLOCKS];
__device__ long long          g_rec[N_EDGES];
__device__ float              g_sum[OUT_FEAT];
__device__ float              g_sumsq[OUT_FEAT];
__device__ int                g_bar_cnt;
__device__ volatile int       g_bar_sense;
__device__ unsigned short     g_wtb_hi[OUT_FEAT * IN_FEAT];
__device__ unsigned short     g_wtb_lo[OUT_FEAT * IN_FEAT];

__device__ __forceinline__ int get_idx(const void* p, int e, int is64) {
    return is64 ? (int)((const long long*)p)[e] : ((const int*)p)[e];
}

__device__ __forceinline__ int sniff_is64(const void* src) {
    const unsigned* p = (const unsigned*)src;
    int is64 = 1;
#pragma unroll
    for (int k = 0; k < 16; k++) is64 &= (p[2 * k + 1] == 0u);
    return is64;
}

__device__ __forceinline__ void grid_barrier(int nblk) {
    __syncthreads();
    if (threadIdx.x == 0) {
        int s = g_bar_sense;
        __threadfence();
        if (atomicAdd(&g_bar_cnt, 1) == nblk - 1) {
            g_bar_cnt = 0;
            __threadfence();
            g_bar_sense = s ^ 1;
        } else {
            while (g_bar_sense == s) { }
        }
    }
    __syncthreads();
}

// --------------- degrees + per-edge dst-rank --------------------------------
__global__ __launch_bounds__(256)
void k_deg(const void* __restrict__ src, const void* __restrict__ dst,
           const float* __restrict__ er) {
    __shared__ int s64;
    if (threadIdx.x == 0) s64 = sniff_is64(src);
    __syncthreads();
    int e = blockIdx.x * blockDim.x + threadIdx.x;
    if (e >= N_EDGES) return;
    float ev = __ldg(er + e);
    int is64 = s64;
    int s = get_idx(src, e, is64);
    int d = get_idx(dst, e, is64);
    if (ev >= P_EDGE) {
        atomicAdd(&g_cnt_src[s], 1);
        int r = atomicAdd(&g_cnt_dst[d], 1);
        g_rank[e] = r;
    }
}

// --------------- single-launch decoupled-lookback scan ----------------------
__global__ __launch_bounds__(SCAN_CHUNK)
void k_scan_lb() {
    const int b    = blockIdx.x;
    const int t    = threadIdx.x;
    const int lane = t & 31;
    const int w    = t >> 5;
    const int i    = b * SCAN_CHUNK + t;

    int v = (i < N_NODES) ? g_cnt_dst[i] : 0;
    int incl = v;
#pragma unroll
    for (int o = 1; o < 32; o <<= 1) {
        int n = __shfl_up_sync(~0u, incl, o);
        if (lane >= o) incl += n;
    }
    __shared__ int ws[SCAN_CHUNK / 32];
    if (lane == 31) ws[w] = incl;
    __syncthreads();
    if (w == 0 && lane < SCAN_CHUNK / 32) {
        int x = ws[lane];
#pragma unroll
        for (int o = 1; o < SCAN_CHUNK / 32; o <<= 1) {
            int n = __shfl_up_sync(0xffu, x, o);
            if (lane >= o) x += n;
        }
        ws[lane] = x;
    }
    __syncthreads();
    int wbase = (w > 0) ? ws[w - 1] : 0;
    int total = ws[SCAN_CHUNK / 32 - 1];
    int lexcl = wbase + incl - v;

    __shared__ int s_excl;
    if (t == 0) {
        if (b == 0) {
            atomicExch(&g_scan[0], ((unsigned long long)total << 2) | 2ull);
            s_excl = 0;
        } else {
            atomicExch(&g_scan[b], ((unsigned long long)total << 2) | 1ull);
        }
    }
    __syncthreads();

    if (b > 0 && w == 0) {
        long long excl = 0;
        int p = b - 1;
        for (;;) {
            int idx = p - lane;
            unsigned long long pk = 0;
            int flag = 2;
            if (idx >= 0) {
                do {
                    pk = *(volatile unsigned long long*)&g_scan[idx];
                    flag = (int)(pk & 3ull);
                } while (flag == 0);
            }
            unsigned pmask = __ballot_sync(~0u, (idx >= 0) && (flag == 2));
            int stop = pmask ? (__ffs(pmask) - 1) : 32;
            long long val = (long long)(pk >> 2);
            long long contrib = ((idx >= 0) && (lane <= stop)) ? val : 0;
#pragma unroll
            for (int o = 16; o > 0; o >>= 1)
                contrib += __shfl_down_sync(~0u, contrib, o);
            contrib = __shfl_sync(~0u, contrib, 0);
            excl += contrib;
            if (stop < 32) break;
            p -= 32;
        }
        if (lane == 0) {
            atomicExch(&g_scan[b],
                       (((unsigned long long)(excl + total)) << 2) | 2ull);
            s_excl = (int)excl;
        }
    }
    __syncthreads();
    int excl = s_excl;

    if (i < N_NODES) {
        int off = excl + lexcl;
        g_off[i] = off;
        g_rs_src[i] = rsqrtf(fmaxf((float)g_cnt_src[i], 1.f));
        g_rs_dst[i] = rsqrtf(fmaxf((float)v, 1.f));
        if (i == N_NODES - 1) g_off[N_NODES] = off + v;
    }
}

// --------------- scatter (atomic-free) + zero BN accumulators ---------------
__global__ __launch_bounds__(256)
void k_scatter(const void* __restrict__ src, const void* __restrict__ dst,
               const float* __restrict__ er) {
    __shared__ int s64;
    if (threadIdx.x == 0) s64 = sniff_is64(src);
    __syncthreads();
    int e = blockIdx.x * blockDim.x + threadIdx.x;
    if (blockIdx.x == 0 && threadIdx.x < OUT_FEAT) {
        g_sum[threadIdx.x] = 0.f;
        g_sumsq[threadIdx.x] = 0.f;
    }
    if (e >= N_EDGES) return;
    float ev = __ldg(er + e);
    int is64 = s64;
    int s = get_idx(src, e, is64);
    int d = get_idx(dst, e, is64);
    if (ev < P_EDGE) return;
    float coef = g_rs_src[s] * g_rs_dst[d];
    int pos = g_off[d] + g_rank[e];
    g_rec[pos] = (long long)(unsigned)s |
                 ((long long)(unsigned)__float_as_int(coef) << 32);
}

// ----------------------------- W^T bf16 hi/lo precompute --------------------
__global__ __launch_bounds__(256)
void k_wprep(const float* __restrict__ W) {
    int idx = blockIdx.x * blockDim.x + threadIdx.x;
    if (idx >= OUT_FEAT * IN_FEAT) return;
    int n = idx >> 8, k = idx & 255;
    float v = W[k * OUT_FEAT + n];
    __nv_bfloat16 hb = __float2bfloat16_rn(v);
    float r = v - __bfloat162float(hb);
    __nv_bfloat16 lb = __float2bfloat16_rn(r);
    g_wtb_hi[idx] = *(unsigned short*)&hb;
    g_wtb_lo[idx] = *(unsigned short*)&lb;
}

// ----------------------------- GEMM: mma.sync bf16 3-pass, fp16 output ------
// Register-lean fragment staging: only B fragments (8 regs) stay live per
// pass; A fragments (4 regs) are re-loaded from smem inside the mt loop.
// Live set ~90 regs -> no spills under launch_bounds(256,2).
#define APITCH 40
#define KCH    32
#define GSM_BYTES (4 * 128 * APITCH * 2)   // 40960

__device__ __forceinline__ void mma16816(float* d, const uint32_t* a,
                                         const uint32_t* b) {
    asm volatile(
        "mma.sync.aligned.m16n8k16.row.col.f32.bf16.bf16.f32 "
        "{%0,%1,%2,%3}, {%4,%5,%6,%7}, {%8,%9}, {%0,%1,%2,%3};"
        : "+f"(d[0]), "+f"(d[1]), "+f"(d[2]), "+f"(d[3])
        : "r"(a[0]), "r"(a[1]), "r"(a[2]), "r"(a[3]), "r"(b[0]), "r"(b[1]));
}

__device__ __forceinline__ void load_afrag(uint32_t* a, const unsigned short* p) {
    a[0] = *(const uint32_t*)p;
    a[1] = *(const uint32_t*)(p + 8 * APITCH);
    a[2] = *(const uint32_t*)(p + 8);
    a[3] = *(const uint32_t*)(p + 8 * APITCH + 8);
}

__global__ __launch_bounds__(256, 2)
void k_gemm_mma(const float* __restrict__ A) {
    extern __shared__ __align__(16) unsigned short sm[];
    unsigned short* Ahi = sm;
    unsigned short* Alo = Ahi + 128 * APITCH;
    unsigned short* Bhi = Alo + 128 * APITCH;
    unsigned short* Blo = Bhi + 128 * APITCH;

    const int tid  = threadIdx.x;
    const int lane = tid & 31;
    const int wid  = tid >> 5;
    const int wm   = wid >> 2;
    const int wn   = wid & 3;
    const int rowb = blockIdx.x * 128;
    const int gr4  = lane >> 2;
    const int kq   = (lane & 3) * 2;

    float acc[4][4][4];
#pragma unroll
    for (int mt = 0; mt < 4; mt++)
#pragma unroll
        for (int nt = 0; nt < 4; nt++)
#pragma unroll
            for (int r = 0; r < 4; r++) acc[mt][nt][r] = 0.f;

    for (int ch = 0; ch < IN_FEAT / KCH; ch++) {
        const int kt = ch * KCH;
#pragma unroll
        for (int it = 0; it < 4; it++) {
            int idx = it * 256 + tid;
            int row = idx >> 3;
            int q   = idx & 7;
            int gr  = rowb + row;
            float4 v = (gr < N_NODES)
                ? ((const float4*)(A + (size_t)gr * IN_FEAT + kt + q * 4))[0]
                : make_float4(0.f, 0.f, 0.f, 0.f);
            __nv_bfloat16 h0 = __float2bfloat16_rn(v.x);
            __nv_bfloat16 h1 = __float2bfloat16_rn(v.y);
            __nv_bfloat16 h2 = __float2bfloat16_rn(v.z);
            __nv_bfloat16 h3 = __float2bfloat16_rn(v.w);
            __nv_bfloat16 l0 = __float2bfloat16_rn(v.x - __bfloat162float(h0));
            __nv_bfloat16 l1 = __float2bfloat16_rn(v.y - __bfloat162float(h1));
            __nv_bfloat16 l2 = __float2bfloat16_rn(v.z - __bfloat162float(h2));
            __nv_bfloat16 l3 = __float2bfloat16_rn(v.w - __bfloat162float(h3));
            uint2 hp, lp;
            hp.x = (uint32_t)*(unsigned short*)&h0 | ((uint32_t)*(unsigned short*)&h1 << 16);
            hp.y = (uint32_t)*(unsigned short*)&h2 | ((uint32_t)*(unsigned short*)&h3 << 16);
            lp.x = (uint32_t)*(unsigned short*)&l0 | ((uint32_t)*(unsigned short*)&l1 << 16);
            lp.y = (uint32_t)*(unsigned short*)&l2 | ((uint32_t)*(unsigned short*)&l3 << 16);
            *(uint2*)(Ahi + row * APITCH + q * 4) = hp;
            *(uint2*)(Alo + row * APITCH + q * 4) = lp;
        }
#pragma unroll
        for (int it = 0; it < 4; it++) {
            int idx = it * 256 + tid;
            int row = idx >> 3;
            int q   = idx & 7;
            uint2 hp = *(const uint2*)(g_wtb_hi + (size_t)row * IN_FEAT + kt + q * 4);
            uint2 lp = *(const uint2*)(g_wtb_lo + (size_t)row * IN_FEAT + kt + q * 4);
            *(uint2*)(Bhi + row * APITCH + q * 4) = hp;
            *(uint2*)(Blo + row * APITCH + q * 4) = lp;
        }
        __syncthreads();

#pragma unroll
        for (int ks = 0; ks < KCH; ks += 16) {
            uint32_t bf[4][2];
            uint32_t af[4];
            // ---- pass 1: A_hi x B_hi
#pragma unroll
            for (int nt = 0; nt < 4; nt++) {
                const unsigned short* ph = Bhi + (wn * 32 + nt * 8 + gr4) * APITCH + ks + kq;
                bf[nt][0] = *(const uint32_t*)ph;
                bf[nt][1] = *(const uint32_t*)(ph + 8);
            }
#pragma unroll
            for (int mt = 0; mt < 4; mt++) {
                load_afrag(af, Ahi + (wm * 64 + mt * 16 + gr4) * APITCH + ks + kq);
#pragma unroll
                for (int nt = 0; nt < 4; nt++)
                    mma16816(acc[mt][nt], af, bf[nt]);
            }
            // ---- pass 2: A_lo x B_hi
#pragma unroll
            for (int mt = 0; mt < 4; mt++) {
                load_afrag(af, Alo + (wm * 64 + mt * 16 + gr4) * APITCH + ks + kq);
#pragma unroll
                for (int nt = 0; nt < 4; nt++)
                    mma16816(acc[mt][nt], af, bf[nt]);
            }
            // ---- pass 3: A_hi x B_lo
#pragma unroll
            for (int nt = 0; nt < 4; nt++) {
                const unsigned short* pl = Blo + (wn * 32 + nt * 8 + gr4) * APITCH + ks + kq;
                bf[nt][0] = *(const uint32_t*)pl;
                bf[nt][1] = *(const uint32_t*)(pl + 8);
            }
#pragma unroll
            for (int mt = 0; mt < 4; mt++) {
                load_afrag(af, Ahi + (wm * 64 + mt * 16 + gr4) * APITCH + ks + kq);
#pragma unroll
                for (int nt = 0; nt < 4; nt++)
                    mma16816(acc[mt][nt], af, bf[nt]);
            }
        }
        __syncthreads();
    }

#pragma unroll
    for (int mt = 0; mt < 4; mt++) {
        int r0 = rowb + wm * 64 + mt * 16 + gr4;
#pragma unroll
        for (int nt = 0; nt < 4; nt++) {
            int c0 = wn * 32 + nt * 8 + (lane & 3) * 2;
            if (r0 < N_NODES)
                *(__half2*)(g_h + (size_t)r0 * OUT_FEAT + c0) =
                    __floats2half2_rn(acc[mt][nt][0], acc[mt][nt][1]);
            if (r0 + 8 < N_NODES)
                *(__half2*)(g_h + (size_t)(r0 + 8) * OUT_FEAT + c0) =
                    __floats2half2_rn(acc[mt][nt][2], acc[mt][nt][3]);
        }
    }
}

// --------- fused: aggregate + BN stats + grid barrier + BN apply + dropout --
__global__ __launch_bounds__(256)
void k_aggfin(const float* __restrict__ b, const float* __restrict__ nr,
              const float* __restrict__ gamma, const float* __restrict__ beta,
              float* __restrict__ out, int nblk) {
    const int lane  = threadIdx.x & 31;
    const int wid   = threadIdx.x >> 5;
    const int wg    = (blockIdx.x * blockDim.x + threadIdx.x) >> 5;
    const int nwarp = nblk * (256 >> 5);

    float4 bb = __ldg(((const float4*)b) + lane);
    float s0 = 0.f, s1 = 0.f, s2 = 0.f, s3 = 0.f;
    float q0 = 0.f, q1 = 0.f, q2 = 0.f, q3 = 0.f;

    for (int node = wg; node < N_NODES; node += nwarp) {
        int beg = g_off[node];
        int end = g_off[node + 1];
        float4 acc = bb;
        int j = beg;
        for (; j + 4 <= end; j += 4) {
            long long r0 = __ldg(g_rec + j + 0);
            long long r1 = __ldg(g_rec + j + 1);
            long long r2 = __ldg(g_rec + j + 2);
            long long r3 = __ldg(g_rec + j + 3);
            const uint2* p0 = (const uint2*)(g_h + (size_t)(unsigned)(int)r0 * OUT_FEAT) + lane;
            const uint2* p1 = (const uint2*)(g_h + (size_t)(unsigned)(int)r1 * OUT_FEAT) + lane;
            const uint2* p2 = (const uint2*)(g_h + (size_t)(unsigned)(int)r2 * OUT_FEAT) + lane;
            const uint2* p3 = (const uint2*)(g_h + (size_t)(unsigned)(int)r3 * OUT_FEAT) + lane;
            uint2 u0 = __ldg(p0);
            uint2 u1 = __ldg(p1);
            uint2 u2 = __ldg(p2);
            uint2 u3 = __ldg(p3);
            float c0 = __int_as_float((int)(r0 >> 32));
            float c1 = __int_as_float((int)(r1 >> 32));
            float c2 = __int_as_float((int)(r2 >> 32));
            float c3 = __int_as_float((int)(r3 >> 32));
            float2 a0 = __half22float2(*(__half2*)&u0.x), b0 = __half22float2(*(__half2*)&u0.y);
            float2 a1 = __half22float2(*(__half2*)&u1.x), b1 = __half22float2(*(__half2*)&u1.y);
            float2 a2 = __half22float2(*(__half2*)&u2.x), b2 = __half22float2(*(__half2*)&u2.y);
            float2 a3 = __half22float2(*(__half2*)&u3.x), b3 = __half22float2(*(__half2*)&u3.y);
            acc.x = fmaf(c0, a0.x, acc.x); acc.y = fmaf(c0, a0.y, acc.y);
            acc.z = fmaf(c0, b0.x, acc.z); acc.w = fmaf(c0, b0.y, acc.w);
            acc.x = fmaf(c1, a1.x, acc.x); acc.y = fmaf(c1, a1.y, acc.y);
            acc.z = fmaf(c1, b1.x, acc.z); acc.w = fmaf(c1, b1.y, acc.w);
            acc.x = fmaf(c2, a2.x, acc.x); acc.y = fmaf(c2, a2.y, acc.y);
            acc.z = fmaf(c2, b2.x, acc.z); acc.w = fmaf(c2, b2.y, acc.w);
            acc.x = fmaf(c3, a3.x, acc.x); acc.y = fmaf(c3, a3.y, acc.y);
            acc.z = fmaf(c3, b3.x, acc.z); acc.w = fmaf(c3, b3.y, acc.w);
        }
        for (; j < end; j++) {
            long long r = __ldg(g_rec + j);
            int   s  = (int)(unsigned)r;
            float cf = __int_as_float((int)(r >> 32));
            uint2 u = __ldg((const uint2*)(g_h + (size_t)s * OUT_FEAT) + lane);
            float2 a = __half22float2(*(__half2*)&u.x);
            float2 c = __half22float2(*(__half2*)&u.y);
            acc.x = fmaf(cf, a.x, acc.x);
            acc.y = fmaf(cf, a.y, acc.y);
            acc.z = fmaf(cf, c.x, acc.z);
            acc.w = fmaf(cf, c.y, acc.w);
        }
        ((float4*)(g_agg + (size_t)node * OUT_FEAT))[lane] = acc;
        s0 += acc.x; s1 += acc.y; s2 += acc.z; s3 += acc.w;
        q0 += acc.x * acc.x; q1 += acc.y * acc.y;
        q2 += acc.z * acc.z; q3 += acc.w * acc.w;
    }

    __shared__ __align__(16) float smS[8][128];
    __shared__ __align__(16) float smQ[8][128];
    ((float4*)&smS[wid][lane * 4])[0] = make_float4(s0, s1, s2, s3);
    ((float4*)&smQ[wid][lane * 4])[0] = make_float4(q0, q1, q2, q3);
    __syncthreads();
    if (threadIdx.x < 128) {
        int c = threadIdx.x;
        float ts = 0.f, tq = 0.f;
#pragma unroll
        for (int w = 0; w < 8; w++) { ts += smS[w][c]; tq += smQ[w][c]; }
        atomicAdd(&g_sum[c], ts);
        atomicAdd(&g_sumsq[c], tq);
    }

    __threadfence();
    grid_barrier(nblk);

    const float inv_n = 1.f / (float)N_NODES;
    const float inv_keep = 1.f / (1.f - P_NODE);
    float scl[4], shf[4];
#pragma unroll
    for (int t = 0; t < 4; t++) {
        int c = lane * 4 + t;
        float mean = g_sum[c] * inv_n;
        float var  = g_sumsq[c] * inv_n - mean * mean;
        float sc   = rsqrtf(var + BN_EPS) * __ldg(gamma + c);
        scl[t] = sc * inv_keep;
        shf[t] = (__ldg(beta + c) - mean * sc) * inv_keep;
    }

    for (int node = wg; node < N_NODES; node += nwarp) {
        float4 a = ((const float4*)(g_agg + (size_t)node * OUT_FEAT))[lane];
        float4 r = __ldg((const float4*)(nr + (size_t)node * OUT_FEAT) + lane);
        float4 y;
        y.x = (r.x >= P_NODE) ? a.x * scl[0] + shf[0] : 0.f;
        y.y = (r.y >= P_NODE) ? a.y * scl[1] + shf[1] : 0.f;
        y.z = (r.z >= P_NODE) ? a.z * scl[2] + shf[2] : 0.f;
        y.w = (r.w >= P_NODE) ? a.w * scl[3] + shf[3] : 0.f;
        ((float4*)(out + (size_t)node * OUT_FEAT))[lane] = y;
    }

    int gi = blockIdx.x * blockDim.x + threadIdx.x;
    if (gi < N_NODES) { g_cnt_src[gi] = 0; g_cnt_dst[gi] = 0; }
    if (gi < SCAN_BLOCKS) g_scan[gi] = 0ull;
}

// ----------------------------- launch ---------------------------------------
extern "C" void kernel_launch(void* const* d_in, const int* in_sizes, int n_in,
                              void* d_out, int out_size) {
    const float* features = (const float*)d_in[0];
    const float* W        = (const float*)d_in[1];
    const float* b        = (const float*)d_in[2];
    const float* gamma    = (const float*)d_in[3];
    const float* beta     = (const float*)d_in[4];
    const void*  src      = d_in[5];
    const void*  dst      = d_in[6];
    const float* er       = (const float*)d_in[7];
    const float* nr       = (const float*)d_in[8];
    float* out            = (float*)d_out;

    static cudaStream_t s_side = nullptr;
    static cudaEvent_t  s_fork = nullptr, s_join = nullptr;
    static int          s_grid = 0;
    if (s_side == nullptr) {
        cudaStreamCreateWithFlags(&s_side, cudaStreamNonBlocking);
        cudaEventCreateWithFlags(&s_fork, cudaEventDisableTiming);
        cudaEventCreateWithFlags(&s_join, cudaEventDisableTiming);
        cudaFuncSetAttribute(k_gemm_mma,
                             cudaFuncAttributeMaxDynamicSharedMemorySize,
                             GSM_BYTES);
        int nsm = 0, occ = 0;
        cudaDeviceGetAttribute(&nsm, cudaDevAttrMultiProcessorCount, 0);
        cudaOccupancyMaxActiveBlocksPerMultiprocessor(&occ, k_aggfin, 256, 0);
        if (nsm <= 0) nsm = 148;
        if (occ <= 0) occ = 1;
        s_grid = nsm * occ;
    }

    // fork: GEMM branch (features/W only) on side stream
    cudaEventRecord(s_fork, 0);
    cudaStreamWaitEvent(s_side, s_fork, 0);
    k_wprep<<<(OUT_FEAT * IN_FEAT + 255) / 256, 256, 0, s_side>>>(W);
    k_gemm_mma<<<(N_NODES + 127) / 128, 256, GSM_BYTES, s_side>>>(features);
    cudaEventRecord(s_join, s_side);

    // main branch: edge chain
    k_deg<<<(N_EDGES + 255) / 256, 256>>>(src, dst, er);
    k_scan_lb<<<SCAN_BLOCKS, SCAN_CHUNK>>>();
    k_scatter<<<(N_EDGES + 255) / 256, 256>>>(src, dst, er);

    // join: fused aggregation + BN + dropout
    cudaStreamWaitEvent(0, s_join, 0);
    k_aggfin<<<s_grid, 256>>>(b, nr, gamma, beta, out, s_grid);
}

// round 15
// speedup vs baseline: 1.1957x; 1.1682x over previous
#include <cuda_runtime.h>
#include <cuda_fp16.h>
#include <cstdint>

#define N_NODES  50000
#define N_EDGES  800000
#define IN_FEAT  256
#define OUT_FEAT 128
#define P_EDGE   0.2f
#define P_NODE   0.1f
#define BN_EPS   1e-5f

#define SCAN_CHUNK  256
#define SCAN_BLOCKS ((N_NODES + SCAN_CHUNK - 1) / SCAN_CHUNK)   // 196

// ----------------------------- scratch (no allocs allowed) ------------------
__device__ __half             g_h[(size_t)N_NODES * OUT_FEAT];
__device__ float              g_agg[(size_t)N_NODES * OUT_FEAT];
__device__ int                g_cnt_src[N_NODES];
__device__ int                g_cnt_dst[N_NODES];
__device__ float              g_rs_src[N_NODES];
__device__ float              g_rs_dst[N_NODES];
__device__ int                g_off[N_NODES + 1];
__device__ int                g_rank[N_EDGES];
__device__ unsigned long long g_scan[SCAN_BLOCKS];
__device__ long long          g_rec[N_EDGES];
__device__ float              g_sum[OUT_FEAT];
__device__ float              g_sumsq[OUT_FEAT];
__device__ int                g_bar_cnt;
__device__ volatile int       g_bar_sense;
__device__ __half             g_wtf[OUT_FEAT * IN_FEAT];   // W^T fp16 [n][k]

__device__ __forceinline__ int get_idx(const void* p, int e, int is64) {
    return is64 ? (int)((const long long*)p)[e] : ((const int*)p)[e];
}

__device__ __forceinline__ int sniff_is64(const void* src) {
    const unsigned* p = (const unsigned*)src;
    int is64 = 1;
#pragma unroll
    for (int k = 0; k < 16; k++) is64 &= (p[2 * k + 1] == 0u);
    return is64;
}

__device__ __forceinline__ void grid_barrier(int nblk) {
    __syncthreads();
    if (threadIdx.x == 0) {
        int s = g_bar_sense;
        __threadfence();
        if (atomicAdd(&g_bar_cnt, 1) == nblk - 1) {
            g_bar_cnt = 0;
            __threadfence();
            g_bar_sense = s ^ 1;
        } else {
            while (g_bar_sense == s) { }
        }
    }
    __syncthreads();
}

// --------------- degrees + per-edge dst-rank --------------------------------
__global__ __launch_bounds__(256)
void k_deg(const void* __restrict__ src, const void* __restrict__ dst,
           const float* __restrict__ er) {
    __shared__ int s64;
    if (threadIdx.x == 0) s64 = sniff_is64(src);
    __syncthreads();
    int e = blockIdx.x * blockDim.x + threadIdx.x;
    if (e >= N_EDGES) return;
    float ev = __ldg(er + e);
    int is64 = s64;
    int s = get_idx(src, e, is64);
    int d = get_idx(dst, e, is64);
    if (ev >= P_EDGE) {
        atomicAdd(&g_cnt_src[s], 1);
        int r = atomicAdd(&g_cnt_dst[d], 1);
        g_rank[e] = r;
    }
}

// --------------- single-launch decoupled-lookback scan ----------------------
__global__ __launch_bounds__(SCAN_CHUNK)
void k_scan_lb() {
    const int b    = blockIdx.x;
    const int t    = threadIdx.x;
    const int lane = t & 31;
    const int w    = t >> 5;
    const int i    = b * SCAN_CHUNK + t;

    int v = (i < N_NODES) ? g_cnt_dst[i] : 0;
    int incl = v;
#pragma unroll
    for (int o = 1; o < 32; o <<= 1) {
        int n = __shfl_up_sync(~0u, incl, o);
        if (lane >= o) incl += n;
    }
    __shared__ int ws[SCAN_CHUNK / 32];
    if (lane == 31) ws[w] = incl;
    __syncthreads();
    if (w == 0 && lane < SCAN_CHUNK / 32) {
        int x = ws[lane];
#pragma unroll
        for (int o = 1; o < SCAN_CHUNK / 32; o <<= 1) {
            int n = __shfl_up_sync(0xffu, x, o);
            if (lane >= o) x += n;
        }
        ws[lane] = x;
    }
    __syncthreads();
    int wbase = (w > 0) ? ws[w - 1] : 0;
    int total = ws[SCAN_CHUNK / 32 - 1];
    int lexcl = wbase + incl - v;

    __shared__ int s_excl;
    if (t == 0) {
        if (b == 0) {
            atomicExch(&g_scan[0], ((unsigned long long)total << 2) | 2ull);
            s_excl = 0;
        } else {
            atomicExch(&g_scan[b], ((unsigned long long)total << 2) | 1ull);
        }
    }
    __syncthreads();

    if (b > 0 && w == 0) {
        long long excl = 0;
        int p = b - 1;
        for (;;) {
            int idx = p - lane;
            unsigned long long pk = 0;
            int flag = 2;
            if (idx >= 0) {
                do {
                    pk = *(volatile unsigned long long*)&g_scan[idx];
                    flag = (int)(pk & 3ull);
                } while (flag == 0);
            }
            unsigned pmask = __ballot_sync(~0u, (idx >= 0) && (flag == 2));
            int stop = pmask ? (__ffs(pmask) - 1) : 32;
            long long val = (long long)(pk >> 2);
            long long contrib = ((idx >= 0) && (lane <= stop)) ? val : 0;
#pragma unroll
            for (int o = 16; o > 0; o >>= 1)
                contrib += __shfl_down_sync(~0u, contrib, o);
            contrib = __shfl_sync(~0u, contrib, 0);
            excl += contrib;
            if (stop < 32) break;
            p -= 32;
        }
        if (lane == 0) {
            atomicExch(&g_scan[b],
                       (((unsigned long long)(excl + total)) << 2) | 2ull);
            s_excl = (int)excl;
        }
    }
    __syncthreads();
    int excl = s_excl;

    if (i < N_NODES) {
        int off = excl + lexcl;
        g_off[i] = off;
        g_rs_src[i] = rsqrtf(fmaxf((float)g_cnt_src[i], 1.f));
        g_rs_dst[i] = rsqrtf(fmaxf((float)v, 1.f));
        if (i == N_NODES - 1) g_off[N_NODES] = off + v;
    }
}

// --------------- scatter (atomic-free) + zero BN accumulators ---------------
__global__ __launch_bounds__(256)
void k_scatter(const void* __restrict__ src, const void* __restrict__ dst,
               const float* __restrict__ er) {
    __shared__ int s64;
    if (threadIdx.x == 0) s64 = sniff_is64(src);
    __syncthreads();
    int e = blockIdx.x * blockDim.x + threadIdx.x;
    if (blockIdx.x == 0 && threadIdx.x < OUT_FEAT) {
        g_sum[threadIdx.x] = 0.f;
        g_sumsq[threadIdx.x] = 0.f;
    }
    if (e >= N_EDGES) return;
    float ev = __ldg(er + e);
    int is64 = s64;
    int s = get_idx(src, e, is64);
    int d = get_idx(dst, e, is64);
    if (ev < P_EDGE) return;
    float coef = g_rs_src[s] * g_rs_dst[d];
    int pos = g_off[d] + g_rank[e];
    g_rec[pos] = (long long)(unsigned)s |
                 ((long long)(unsigned)__float_as_int(coef) << 32);
}

// ----------------------------- W^T fp16 precompute --------------------------
__global__ __launch_bounds__(256)
void k_wprep(const float* __restrict__ W) {
    int idx = blockIdx.x * blockDim.x + threadIdx.x;
    if (idx >= OUT_FEAT * IN_FEAT) return;
    int n = idx >> 8, k = idx & 255;
    g_wtf[idx] = __float2half_rn(W[k * OUT_FEAT + n]);
}

// ----------------------------- GEMM: single-pass fp16 mma.sync --------------
// CTA 128x128, 8 warps (2m x 4n), K chunks of 32, fp16 A & W, fp32 acc.
#define APITCH 40
#define KCH    32
#define GSM_BYTES (2 * 128 * APITCH * 2)   // Af + Bf = 20480

__device__ __forceinline__ void mma16816f(float* d, const uint32_t* a,
                                          const uint32_t* b) {
    asm volatile(
        "mma.sync.aligned.m16n8k16.row.col.f32.f16.f16.f32 "
        "{%0,%1,%2,%3}, {%4,%5,%6,%7}, {%8,%9}, {%0,%1,%2,%3};"
        : "+f"(d[0]), "+f"(d[1]), "+f"(d[2]), "+f"(d[3])
        : "r"(a[0]), "r"(a[1]), "r"(a[2]), "r"(a[3]), "r"(b[0]), "r"(b[1]));
}

__global__ __launch_bounds__(256, 2)
void k_gemm_mma(const float* __restrict__ A) {
    extern __shared__ __align__(16) __half sm[];
    __half* Af = sm;
    __half* Bf = Af + 128 * APITCH;

    const int tid  = threadIdx.x;
    const int lane = tid & 31;
    const int wid  = tid >> 5;
    const int wm   = wid >> 2;
    const int wn   = wid & 3;
    const int rowb = blockIdx.x * 128;
    const int gr4  = lane >> 2;
    const int kq   = (lane & 3) * 2;

    float acc[4][4][4];
#pragma unroll
    for (int mt = 0; mt < 4; mt++)
#pragma unroll
        for (int nt = 0; nt < 4; nt++)
#pragma unroll
            for (int r = 0; r < 4; r++) acc[mt][nt][r] = 0.f;

    for (int ch = 0; ch < IN_FEAT / KCH; ch++) {
        const int kt = ch * KCH;
        // ---- A chunk: 128 rows x 32 k, fp32 -> fp16
#pragma unroll
        for (int it = 0; it < 4; it++) {
            int idx = it * 256 + tid;
            int row = idx >> 3;
            int q   = idx & 7;
            int gr  = rowb + row;
            float4 v = (gr < N_NODES)
                ? ((const float4*)(A + (size_t)gr * IN_FEAT + kt + q * 4))[0]
                : make_float4(0.f, 0.f, 0.f, 0.f);
            __half2 h01 = __floats2half2_rn(v.x, v.y);
            __half2 h23 = __floats2half2_rn(v.z, v.w);
            uint2 pk;
            pk.x = *(uint32_t*)&h01;
            pk.y = *(uint32_t*)&h23;
            *(uint2*)(Af + row * APITCH + q * 4) = pk;
        }
        // ---- B chunk: 128 n-rows x 32 k (precomputed fp16)
#pragma unroll
        for (int it = 0; it < 4; it++) {
            int idx = it * 256 + tid;
            int row = idx >> 3;
            int q   = idx & 7;
            uint2 pk = *(const uint2*)(g_wtf + (size_t)row * IN_FEAT + kt + q * 4);
            *(uint2*)(Bf + row * APITCH + q * 4) = pk;
        }
        __syncthreads();

#pragma unroll
        for (int ks = 0; ks < KCH; ks += 16) {
            uint32_t bf[4][2];
#pragma unroll
            for (int nt = 0; nt < 4; nt++) {
                const __half* ph = Bf + (wn * 32 + nt * 8 + gr4) * APITCH + ks + kq;
                bf[nt][0] = *(const uint32_t*)ph;
                bf[nt][1] = *(const uint32_t*)(ph + 8);
            }
            uint32_t af[4][4];
#pragma unroll
            for (int mt = 0; mt < 4; mt++) {
                const __half* pa = Af + (wm * 64 + mt * 16 + gr4) * APITCH + ks + kq;
                af[mt][0] = *(const uint32_t*)pa;
                af[mt][1] = *(const uint32_t*)(pa + 8 * APITCH);
                af[mt][2] = *(const uint32_t*)(pa + 8);
                af[mt][3] = *(const uint32_t*)(pa + 8 * APITCH + 8);
            }
#pragma unroll
            for (int mt = 0; mt < 4; mt++)
#pragma unroll
                for (int nt = 0; nt < 4; nt++)
                    mma16816f(acc[mt][nt], af[mt], bf[nt]);
        }
        __syncthreads();
    }

#pragma unroll
    for (int mt = 0; mt < 4; mt++) {
        int r0 = rowb + wm * 64 + mt * 16 + gr4;
#pragma unroll
        for (int nt = 0; nt < 4; nt++) {
            int c0 = wn * 32 + nt * 8 + (lane & 3) * 2;
            if (r0 < N_NODES)
                *(__half2*)(g_h + (size_t)r0 * OUT_FEAT + c0) =
                    __floats2half2_rn(acc[mt][nt][0], acc[mt][nt][1]);
            if (r0 + 8 < N_NODES)
                *(__half2*)(g_h + (size_t)(r0 + 8) * OUT_FEAT + c0) =
                    __floats2half2_rn(acc[mt][nt][2], acc[mt][nt][3]);
        }
    }
}

// --------- fused: aggregate (8-deep) + BN stats + barrier + BN + dropout ----
__global__ __launch_bounds__(256)
void k_aggfin(const float* __restrict__ b, const float* __restrict__ nr,
              const float* __restrict__ gamma, const float* __restrict__ beta,
              float* __restrict__ out, int nblk) {
    const int lane  = threadIdx.x & 31;
    const int wid   = threadIdx.x >> 5;
    const int wg    = (blockIdx.x * blockDim.x + threadIdx.x) >> 5;
    const int nwarp = nblk * (256 >> 5);

    float4 bb = __ldg(((const float4*)b) + lane);
    float s0 = 0.f, s1 = 0.f, s2 = 0.f, s3 = 0.f;
    float q0 = 0.f, q1 = 0.f, q2 = 0.f, q3 = 0.f;

    for (int node = wg; node < N_NODES; node += nwarp) {
        int beg = g_off[node];
        int end = g_off[node + 1];
        float4 acc = bb;
        int j = beg;
        // 8-deep pipeline: batch record loads, batch gathers, then FMAs
        for (; j + 8 <= end; j += 8) {
            long long r[8];
#pragma unroll
            for (int i = 0; i < 8; i++) r[i] = __ldg(g_rec + j + i);
            uint2 u[8];
#pragma unroll
            for (int i = 0; i < 8; i++)
                u[i] = __ldg((const uint2*)(g_h +
                        (size_t)(unsigned)(int)r[i] * OUT_FEAT) + lane);
#pragma unroll
            for (int i = 0; i < 8; i++) {
                float cf = __int_as_float((int)(r[i] >> 32));
                float2 a = __half22float2(*(__half2*)&u[i].x);
                float2 c = __half22float2(*(__half2*)&u[i].y);
                acc.x = fmaf(cf, a.x, acc.x);
                acc.y = fmaf(cf, a.y, acc.y);
                acc.z = fmaf(cf, c.x, acc.z);
                acc.w = fmaf(cf, c.y, acc.w);
            }
        }
        for (; j < end; j++) {
            long long r = __ldg(g_rec + j);
            int   s  = (int)(unsigned)r;
            float cf = __int_as_float((int)(r >> 32));
            uint2 u = __ldg((const uint2*)(g_h + (size_t)s * OUT_FEAT) + lane);
            float2 a = __half22float2(*(__half2*)&u.x);
            float2 c = __half22float2(*(__half2*)&u.y);
            acc.x = fmaf(cf, a.x, acc.x);
            acc.y = fmaf(cf, a.y, acc.y);
            acc.z = fmaf(cf, c.x, acc.z);
            acc.w = fmaf(cf, c.y, acc.w);
        }
        ((float4*)(g_agg + (size_t)node * OUT_FEAT))[lane] = acc;
        s0 += acc.x; s1 += acc.y; s2 += acc.z; s3 += acc.w;
        q0 += acc.x * acc.x; q1 += acc.y * acc.y;
        q2 += acc.z * acc.z; q3 += acc.w * acc.w;
    }

    __shared__ __align__(16) float smS[8][128];
    __shared__ __align__(16) float smQ[8][128];
    ((float4*)&smS[wid][lane * 4])[0] = make_float4(s0, s1, s2, s3);
    ((float4*)&smQ[wid][lane * 4])[0] = make_float4(q0, q1, q2, q3);
    __syncthreads();
    if (threadIdx.x < 128) {
        int c = threadIdx.x;
        float ts = 0.f, tq = 0.f;
#pragma unroll
        for (int w = 0; w < 8; w++) { ts += smS[w][c]; tq += smQ[w][c]; }
        atomicAdd(&g_sum[c], ts);
        atomicAdd(&g_sumsq[c], tq);
    }

    __threadfence();
    grid_barrier(nblk);

    const float inv_n = 1.f / (float)N_NODES;
    const float inv_keep = 1.f / (1.f - P_NODE);
    float scl[4], shf[4];
#pragma unroll
    for (int t = 0; t < 4; t++) {
        int c = lane * 4 + t;
        float mean = g_sum[c] * inv_n;
        float var  = g_sumsq[c] * inv_n - mean * mean;
        float sc   = rsqrtf(var + BN_EPS) * __ldg(gamma + c);
        scl[t] = sc * inv_keep;
        shf[t] = (__ldg(beta + c) - mean * sc) * inv_keep;
    }

    for (int node = wg; node < N_NODES; node += nwarp) {
        float4 a = ((const float4*)(g_agg + (size_t)node * OUT_FEAT))[lane];
        float4 r = __ldg((const float4*)(nr + (size_t)node * OUT_FEAT) + lane);
        float4 y;
        y.x = (r.x >= P_NODE) ? a.x * scl[0] + shf[0] : 0.f;
        y.y = (r.y >= P_NODE) ? a.y * scl[1] + shf[1] : 0.f;
        y.z = (r.z >= P_NODE) ? a.z * scl[2] + shf[2] : 0.f;
        y.w = (r.w >= P_NODE) ? a.w * scl[3] + shf[3] : 0.f;
        ((float4*)(out + (size_t)node * OUT_FEAT))[lane] = y;
    }

    int gi = blockIdx.x * blockDim.x + threadIdx.x;
    if (gi < N_NODES) { g_cnt_src[gi] = 0; g_cnt_dst[gi] = 0; }
    if (gi < SCAN_BLOCKS) g_scan[gi] = 0ull;
}

// ----------------------------- launch ---------------------------------------
extern "C" void kernel_launch(void* const* d_in, const int* in_sizes, int n_in,
                              void* d_out, int out_size) {
    const float* features = (const float*)d_in[0];
    const float* W        = (const float*)d_in[1];
    const float* b        = (const float*)d_in[2];
    const float* gamma    = (const float*)d_in[3];
    const float* beta     = (const float*)d_in[4];
    const void*  src      = d_in[5];
    const void*  dst      = d_in[6];
    const float* er       = (const float*)d_in[7];
    const float* nr       = (const float*)d_in[8];
    float* out            = (float*)d_out;

    static cudaStream_t s_side = nullptr;
    static cudaEvent_t  s_fork = nullptr, s_join = nullptr;
    static int          s_grid = 0;
    if (s_side == nullptr) {
        cudaStreamCreateWithFlags(&s_side, cudaStreamNonBlocking);
        cudaEventCreateWithFlags(&s_fork, cudaEventDisableTiming);
        cudaEventCreateWithFlags(&s_join, cudaEventDisableTiming);
        cudaFuncSetAttribute(k_gemm_mma,
                             cudaFuncAttributeMaxDynamicSharedMemorySize,
                             GSM_BYTES);
        int nsm = 0, occ = 0;
        cudaDeviceGetAttribute(&nsm, cudaDevAttrMultiProcessorCount, 0);
        cudaOccupancyMaxActiveBlocksPerMultiprocessor(&occ, k_aggfin, 256, 0);
        if (nsm <= 0) nsm = 148;
        if (occ <= 0) occ = 1;
        s_grid = nsm * occ;
    }

    // fork: GEMM branch (features/W only) on side stream
    cudaEventRecord(s_fork, 0);
    cudaStreamWaitEvent(s_side, s_fork, 0);
    k_wprep<<<(OUT_FEAT * IN_FEAT + 255) / 256, 256, 0, s_side>>>(W);
    k_gemm_mma<<<(N_NODES + 127) / 128, 256, GSM_BYTES, s_side>>>(features);
    cudaEventRecord(s_join, s_side);

    // main branch: edge chain
    k_deg<<<(N_EDGES + 255) / 256, 256>>>(src, dst, er);
    k_scan_lb<<<SCAN_BLOCKS, SCAN_CHUNK>>>();
    k_scatter<<<(N_EDGES + 255) / 256, 256>>>(src, dst, er);

    // join: fused aggregation + BN + dropout
    cudaStreamWaitEvent(0, s_join, 0);
    k_aggfin<<<s_grid, 256>>>(b, nr, gamma, beta, out, s_grid);
}